// round 4
// baseline (speedup 1.0000x reference)
#include <cuda_runtime.h>
#include <stdint.h>

#define NN    8192
#define KSEL  64
#define NT    256
#define EPT4  8            // float4 elements per thread (NN / NT / 4)
#define CAP   512          // candidate capacity (mean ~154, sigma ~12 at c=2.35)
#define MARGIN_ULPS 256u

// Bit-exact replica of XLA's EmitFastTanh (f32, with_fma=true variant).
__device__ __forceinline__ float xla_tanh(float x) {
    const float pc = 7.99881172180175781f;
    float xc = fminf(fmaxf(x, -pc), pc);
    float x2 = __fmul_rn(xc, xc);
    float num = -2.76076847742355e-16f;
    num = __fmaf_rn(x2, num, 2.00018790482477e-13f);
    num = __fmaf_rn(x2, num, -8.60467152213735e-11f);
    num = __fmaf_rn(x2, num, 5.12229709037114e-08f);
    num = __fmaf_rn(x2, num, 1.48572235717979e-05f);
    num = __fmaf_rn(x2, num, 6.37261928875436e-04f);
    num = __fmaf_rn(x2, num, 4.89352455891786e-03f);
    num = __fmul_rn(xc, num);
    float den = 1.19825839466702e-06f;
    den = __fmaf_rn(x2, den, 1.18534705686654e-04f);
    den = __fmaf_rn(x2, den, 2.26843463243900e-03f);
    den = __fmaf_rn(x2, den, 4.89352518554385e-03f);
    float r = __fdiv_rn(num, den);
    return (fabsf(x) < 0.0004f) ? x : r;
}

// packed: (key << 13) | (8191 - idx). Larger packed == better in top_k order
// (larger |adj| key, ties broken by lower index). Values are unique (idx unique).
__device__ __forceinline__ unsigned long long pack_ki(uint32_t key, uint32_t idx) {
    return ((unsigned long long)key << 13) | (8191u - idx);
}

__global__ __launch_bounds__(NT, 6) void topk_tanh_kernel(
    const float* __restrict__ A, float* __restrict__ out)
{
    __shared__ unsigned long long s_pack[CAP];  // raw (A_bits<<32|idx), then packed
    __shared__ float              s_val[CAP];   // signed adj value
    __shared__ uint32_t           s_cnt;
    __shared__ unsigned long long s_P;

    const int t   = threadIdx.x;
    const int row = blockIdx.x;
    const float* rowA = A + (size_t)row * NN;
    const float4* rp = (const float4*)rowA;
    float4* op = (float4*)(out + (size_t)row * NN);

    if (t == 0) s_cnt = 0;
    __syncthreads();

    // ---- Phase 1: stream row: |A|-bit candidate filter + fused zero-fill ----
    uint32_t tb = __float_as_uint(2.35f);     // |A| threshold bits (abs-bit compare)
    const float4 z4 = make_float4(0.f, 0.f, 0.f, 0.f);
#pragma unroll
    for (int i = 0; i < EPT4; i++) {
        const int b4 = i * NT + t;
        float4 v = rp[b4];
        op[b4] = z4;                           // zero-fill (selection-independent)
        const uint32_t idx0 = (uint32_t)(b4 * 4);
        uint32_t b0 = __float_as_uint(v.x), b1 = __float_as_uint(v.y);
        uint32_t b2 = __float_as_uint(v.z), b3 = __float_as_uint(v.w);
        if ((b0 & 0x7fffffffu) > tb) { uint32_t p = atomicAdd(&s_cnt, 1u); if (p < CAP) s_pack[p] = ((unsigned long long)b0 << 32) | (idx0 + 0u); }
        if ((b1 & 0x7fffffffu) > tb) { uint32_t p = atomicAdd(&s_cnt, 1u); if (p < CAP) s_pack[p] = ((unsigned long long)b1 << 32) | (idx0 + 1u); }
        if ((b2 & 0x7fffffffu) > tb) { uint32_t p = atomicAdd(&s_cnt, 1u); if (p < CAP) s_pack[p] = ((unsigned long long)b2 << 32) | (idx0 + 2u); }
        if ((b3 & 0x7fffffffu) > tb) { uint32_t p = atomicAdd(&s_cnt, 1u); if (p < CAP) s_pack[p] = ((unsigned long long)b3 << 32) | (idx0 + 3u); }
    }
    __syncthreads();
    uint32_t cnt = s_cnt;

    // ---- Rare: count out of [K, CAP] -> bisect |A|-bit threshold (global re-read)
    if (cnt < KSEL || cnt > CAP) {
        uint32_t lo = 0u, hi = 0x7f800000u;
        if (cnt < KSEL) hi = tb; else lo = tb;
        for (int iter = 0; iter < 34; iter++) {
            uint32_t tk = lo + ((hi - lo) >> 1);
            __syncthreads();
            if (t == 0) s_cnt = 0;
            __syncthreads();
            for (int j = t; j < NN; j += NT) {
                uint32_t b = __float_as_uint(rowA[j]);
                if ((b & 0x7fffffffu) > tk) {
                    uint32_t p = atomicAdd(&s_cnt, 1u);
                    if (p < CAP) s_pack[p] = ((unsigned long long)b << 32) | (uint32_t)j;
                }
            }
            __syncthreads();
            cnt = s_cnt;
            tb = tk;
            if (cnt >= KSEL && cnt <= CAP) break;
            if (cnt < KSEL) hi = tk; else lo = tk;
            if (hi - lo <= 1u) break;
        }
        if (cnt > CAP) cnt = CAP;   // degenerate massive-tie guard
    }
    const uint32_t c = cnt;

    // ---- Phase 2: exact tanh keys for candidates, in-place repack -----------
    for (uint32_t i = t; i < c; i += NT) {
        unsigned long long raw = s_pack[i];
        float a = __uint_as_float((uint32_t)(raw >> 32));
        uint32_t idx = (uint32_t)(raw & 0xffffffffu);
        float adj = xla_tanh(3.0f * a);
        uint32_t key = __float_as_uint(adj) & 0x7fffffffu;
        s_pack[i] = pack_ki(key, idx);
        s_val[i]  = adj;
    }
    __syncthreads();

    // ---- Phase 3: rank-select 64th largest packed among candidates ----------
    if (c >= KSEL) {
        for (uint32_t i = t; i < c; i += NT) {
            unsigned long long me = s_pack[i];
            uint32_t r = 0;
            for (uint32_t j = 0; j < c; j++) r += (s_pack[j] > me);
            if (r == KSEL - 1) s_P = me;
        }
    } else if (t == 0) {
        s_P = 0ull;   // < K nonzero |A|: select all candidates (rest are exact 0)
    }
    __syncthreads();
    unsigned long long P = s_P;
    uint32_t selCnt = c;

    // ---- Safety check: can any excluded element (|A| <= tb) reach P? --------
    // Excluded elements have key <= key(tanh(3*tb)) + slop. If the provisional
    // threshold key clears that with margin, fast path is exact. Otherwise do
    // an exact full-row rescan collecting everything with packed >= P_prov.
    {
        float tfl = __uint_as_float(tb);
        uint32_t keysafe = (__float_as_uint(xla_tanh(3.0f * tfl)) & 0x7fffffffu) + MARGIN_ULPS;
        uint32_t Tkey = (uint32_t)(P >> 13);
        if (c >= KSEL && Tkey <= keysafe) {
            __syncthreads();
            if (t == 0) s_cnt = 0;
            __syncthreads();
            for (int j = t; j < NN; j += NT) {
                float adj = xla_tanh(3.0f * rowA[j]);
                uint32_t key = __float_as_uint(adj) & 0x7fffffffu;
                unsigned long long pk = pack_ki(key, (uint32_t)j);
                if (pk >= P) {
                    uint32_t p = atomicAdd(&s_cnt, 1u);
                    if (p < CAP) { s_pack[p] = pk; s_val[p] = adj; }
                }
            }
            __syncthreads();
            uint32_t c2 = s_cnt; if (c2 > CAP) c2 = CAP;
            for (uint32_t i = t; i < c2; i += NT) {
                unsigned long long me = s_pack[i];
                uint32_t r = 0;
                for (uint32_t j = 0; j < c2; j++) r += (s_pack[j] > me);
                if (r == KSEL - 1) s_P = me;
            }
            __syncthreads();
            P = s_P;
            selCnt = c2;
        }
    }

    // ---- Phase 4: scatter the exactly-K selected values ---------------------
    // Zero-fill happened before all the barriers above; same-address ordering
    // across __syncthreads makes these stores win.
    for (uint32_t i = t; i < selCnt; i += NT) {
        unsigned long long pk = s_pack[i];
        if (pk >= P) {
            uint32_t idx = 8191u - (uint32_t)(pk & 8191u);
            out[(size_t)row * NN + idx] = s_val[i];
        }
    }
}

extern "C" void kernel_launch(void* const* d_in, const int* in_sizes, int n_in,
                              void* d_out, int out_size)
{
    const float* A = nullptr;
    for (int i = 0; i < n_in; i++)
        if (in_sizes[i] == NN * NN) A = (const float*)d_in[i];
    float* out = (float*)d_out;
    topk_tanh_kernel<<<NN, NT>>>(A, out);
}

// round 5
// speedup vs baseline: 2.0857x; 2.0857x over previous
#include <cuda_runtime.h>
#include <stdint.h>

#define NN    8192
#define KSEL  64
#define NT    256
#define EPT4  8            // float4 elements per thread (NN / NT / 4)
#define CAP   512          // candidate capacity (mean ~154, sigma ~12 at c=2.35)
#define MARGIN_ULPS 8u     // R3 bug: 256 made the "rare" rescan fire every row

// Bit-exact replica of XLA's EmitFastTanh (f32, with_fma=true variant).
__device__ __forceinline__ float xla_tanh(float x) {
    const float pc = 7.99881172180175781f;
    float xc = fminf(fmaxf(x, -pc), pc);
    float x2 = __fmul_rn(xc, xc);
    float num = -2.76076847742355e-16f;
    num = __fmaf_rn(x2, num, 2.00018790482477e-13f);
    num = __fmaf_rn(x2, num, -8.60467152213735e-11f);
    num = __fmaf_rn(x2, num, 5.12229709037114e-08f);
    num = __fmaf_rn(x2, num, 1.48572235717979e-05f);
    num = __fmaf_rn(x2, num, 6.37261928875436e-04f);
    num = __fmaf_rn(x2, num, 4.89352455891786e-03f);
    num = __fmul_rn(xc, num);
    float den = 1.19825839466702e-06f;
    den = __fmaf_rn(x2, den, 1.18534705686654e-04f);
    den = __fmaf_rn(x2, den, 2.26843463243900e-03f);
    den = __fmaf_rn(x2, den, 4.89352518554385e-03f);
    float r = __fdiv_rn(num, den);
    return (fabsf(x) < 0.0004f) ? x : r;
}

// packed: (key << 13) | (8191 - idx). Larger packed == better in top_k order
// (larger |adj| key, ties broken by lower index). Values unique (idx unique).
__device__ __forceinline__ unsigned long long pack_ki(uint32_t key, uint32_t idx) {
    return ((unsigned long long)key << 13) | (8191u - idx);
}

__global__ __launch_bounds__(NT, 6) void topk_tanh_kernel(
    const float* __restrict__ A, float* __restrict__ out)
{
    __shared__ unsigned long long s_pack[CAP];  // raw (A_bits<<32|idx), then packed
    __shared__ float              s_val[CAP];   // signed adj value
    __shared__ uint32_t           s_cnt;
    __shared__ unsigned long long s_P;

    const int t   = threadIdx.x;
    const int row = blockIdx.x;
    const float* rowA = A + (size_t)row * NN;
    const float4* rp = (const float4*)rowA;
    float4* op = (float4*)(out + (size_t)row * NN);

    if (t == 0) s_cnt = 0;
    __syncthreads();

    // ---- Phase 1: stream row: |A|-bit candidate filter + fused zero-fill ----
    uint32_t tb = __float_as_uint(2.35f);     // |A| threshold bits (abs-bit compare)
    const float4 z4 = make_float4(0.f, 0.f, 0.f, 0.f);
#pragma unroll
    for (int i = 0; i < EPT4; i++) {
        const int b4 = i * NT + t;
        float4 v = rp[b4];
        op[b4] = z4;                           // zero-fill (selection-independent)
        const uint32_t idx0 = (uint32_t)(b4 * 4);
        uint32_t b0 = __float_as_uint(v.x), b1 = __float_as_uint(v.y);
        uint32_t b2 = __float_as_uint(v.z), b3 = __float_as_uint(v.w);
        if ((b0 & 0x7fffffffu) > tb) { uint32_t p = atomicAdd(&s_cnt, 1u); if (p < CAP) s_pack[p] = ((unsigned long long)b0 << 32) | (idx0 + 0u); }
        if ((b1 & 0x7fffffffu) > tb) { uint32_t p = atomicAdd(&s_cnt, 1u); if (p < CAP) s_pack[p] = ((unsigned long long)b1 << 32) | (idx0 + 1u); }
        if ((b2 & 0x7fffffffu) > tb) { uint32_t p = atomicAdd(&s_cnt, 1u); if (p < CAP) s_pack[p] = ((unsigned long long)b2 << 32) | (idx0 + 2u); }
        if ((b3 & 0x7fffffffu) > tb) { uint32_t p = atomicAdd(&s_cnt, 1u); if (p < CAP) s_pack[p] = ((unsigned long long)b3 << 32) | (idx0 + 3u); }
    }
    __syncthreads();
    uint32_t cnt = s_cnt;

    // ---- Rare: count out of [K, CAP] -> bisect |A|-bit threshold (global re-read)
    if (__builtin_expect(cnt < KSEL || cnt > CAP, 0)) {
        uint32_t lo = 0u, hi = 0x7f800000u;
        if (cnt < KSEL) hi = tb; else lo = tb;
        for (int iter = 0; iter < 34; iter++) {
            uint32_t tk = lo + ((hi - lo) >> 1);
            __syncthreads();
            if (t == 0) s_cnt = 0;
            __syncthreads();
            for (int j = t; j < NN; j += NT) {
                uint32_t b = __float_as_uint(rowA[j]);
                if ((b & 0x7fffffffu) > tk) {
                    uint32_t p = atomicAdd(&s_cnt, 1u);
                    if (p < CAP) s_pack[p] = ((unsigned long long)b << 32) | (uint32_t)j;
                }
            }
            __syncthreads();
            cnt = s_cnt;
            tb = tk;
            if (cnt >= KSEL && cnt <= CAP) break;
            if (cnt < KSEL) hi = tk; else lo = tk;
            if (hi - lo <= 1u) break;
        }
        if (cnt > CAP) cnt = CAP;   // degenerate massive-tie guard
    }
    const uint32_t c = cnt;

    // ---- Phase 2: exact tanh keys for candidates, in-place repack -----------
    for (uint32_t i = t; i < c; i += NT) {
        unsigned long long raw = s_pack[i];
        float a = __uint_as_float((uint32_t)(raw >> 32));
        uint32_t idx = (uint32_t)(raw & 0xffffffffu);
        float adj = xla_tanh(3.0f * a);
        uint32_t key = __float_as_uint(adj) & 0x7fffffffu;
        s_pack[i] = pack_ki(key, idx);
        s_val[i]  = adj;
    }
    __syncthreads();

    // ---- Phase 3: rank-select 64th largest packed among candidates ----------
    if (c >= KSEL) {
        for (uint32_t i = t; i < c; i += NT) {
            unsigned long long me = s_pack[i];
            uint32_t r = 0;
            for (uint32_t j = 0; j < c; j++) r += (s_pack[j] > me);
            if (r == KSEL - 1) s_P = me;
        }
    } else if (t == 0) {
        s_P = 0ull;   // < K nonzero |A|: select all candidates (rest exact 0)
    }
    __syncthreads();
    unsigned long long P = s_P;
    uint32_t selCnt = c;

    // ---- Safety check: can any excluded element (|A| <= tb) reach P? --------
    // Excluded keys <= key(xla_tanh(3*tb)) + small slop (approx is ~monotone to
    // a couple ulps). If the provisional threshold clears that with margin, the
    // fast path is exact. Otherwise: exact full-row rescan for packed >= P.
    {
        float tfl = __uint_as_float(tb);
        uint32_t keysafe = (__float_as_uint(xla_tanh(3.0f * tfl)) & 0x7fffffffu) + MARGIN_ULPS;
        uint32_t Tkey = (uint32_t)(P >> 13);
        if (__builtin_expect(c >= KSEL && Tkey <= keysafe, 0)) {
            __syncthreads();
            if (t == 0) s_cnt = 0;
            __syncthreads();
            for (int j = t; j < NN; j += NT) {
                float adj = xla_tanh(3.0f * rowA[j]);
                uint32_t key = __float_as_uint(adj) & 0x7fffffffu;
                unsigned long long pk = pack_ki(key, (uint32_t)j);
                if (pk >= P) {
                    uint32_t p = atomicAdd(&s_cnt, 1u);
                    if (p < CAP) { s_pack[p] = pk; s_val[p] = adj; }
                }
            }
            __syncthreads();
            uint32_t c2 = s_cnt; if (c2 > CAP) c2 = CAP;
            for (uint32_t i = t; i < c2; i += NT) {
                unsigned long long me = s_pack[i];
                uint32_t r = 0;
                for (uint32_t j = 0; j < c2; j++) r += (s_pack[j] > me);
                if (r == KSEL - 1) s_P = me;
            }
            __syncthreads();
            P = s_P;
            selCnt = c2;
        }
    }

    // ---- Phase 4: scatter the exactly-K selected values ---------------------
    // Zero-fill happened before the barriers above; __syncthreads orders the
    // same-address global stores within the CTA, so these stores win.
    for (uint32_t i = t; i < selCnt; i += NT) {
        unsigned long long pk = s_pack[i];
        if (pk >= P) {
            uint32_t idx = 8191u - (uint32_t)(pk & 8191u);
            out[(size_t)row * NN + idx] = s_val[i];
        }
    }
}

extern "C" void kernel_launch(void* const* d_in, const int* in_sizes, int n_in,
                              void* d_out, int out_size)
{
    const float* A = nullptr;
    for (int i = 0; i < n_in; i++)
        if (in_sizes[i] == NN * NN) A = (const float*)d_in[i];
    float* out = (float*)d_out;
    topk_tanh_kernel<<<NN, NT>>>(A, out);
}